// round 6
// baseline (speedup 1.0000x reference)
#include <cuda_runtime.h>
#include <math.h>
#include <stdint.h>

// ---------------- problem constants ----------------
#define H_IN 2048
#define W_IN 2048
#define P1   1023            // after conv1(2046) + maxpool2
#define C2   1021            // after conv2
#define C3   1019            // after conv3
#define NPIX (C3*C3)         // 1038361
#define NBINS 8192
#define CANDMAX 4096
#define KTOP 512

typedef unsigned long long ull;

// ---------------- scratch (device globals) ----------
__device__ float g_pool1[10 * P1 * P1];
__device__ float g_h2[16 * C2 * C2];
__device__ float g_prob[NPIX];
__device__ float4 g_reg[NPIX];
__device__ int   g_hist[NBINS];
__device__ int   g_cut;
__device__ int   g_cnt;
__device__ unsigned long long g_cand[CANDMAX];
__device__ float g_box5[KTOP * 5];
__device__ unsigned g_mask0[KTOP * 16];
__device__ unsigned g_mask1[KTOP * 16];
__device__ float g_stage[6632];
__device__ ull   g_stage2[462];
// duplicated {w,w} weights, padded to 10 per (c,o) group for 16B-aligned LDS.128
__device__ float4 g_wd2[10 * 16 * 10 / 2];   // 800 float4
__device__ float4 g_wd3[16 * 32 * 10 / 2];   // 2560 float4

// ---------------- packed constant scalars -------
#define OW1 0
#define OB1 270
#define OP1 280
#define OW2 290
#define OB2 1730
#define OP2 1746
#define OW3 1762
#define OB3 6370
#define OP3 6402
#define OWA 6434
#define OBA 6498
#define OWB 6500
#define OBB 6628
#define NCONST 6632
__constant__ float cAll[NCONST];
// duplicated {w,w} pairs: k1 weights (270), head wa (64), head wb (128)
__constant__ ull cDup[462];

#define CB1(i) cAll[OB1 + (i)]
#define CP1(i) cAll[OP1 + (i)]
#define CB2(i) cAll[OB2 + (i)]
#define CP2(i) cAll[OP2 + (i)]
#define CB3(i) cAll[OB3 + (i)]
#define CP3(i) cAll[OP3 + (i)]
#define CBA(i) cAll[OBA + (i)]
#define CBB(i) cAll[OBB + (i)]
#define D1(i)  cDup[(i)]
#define DWA(i) cDup[270 + (i)]
#define DWB(i) cDup[334 + (i)]

// ---------------- f32x2 helpers ----------------
__device__ __forceinline__ ull pk2(float lo, float hi) {
    ull r; asm("mov.b64 %0, {%1, %2};" : "=l"(r) : "f"(lo), "f"(hi)); return r;
}
__device__ __forceinline__ void up2(float& lo, float& hi, ull v) {
    asm("mov.b64 {%0, %1}, %2;" : "=f"(lo), "=f"(hi) : "l"(v));
}
__device__ __forceinline__ void ffma2(ull& d, ull a, ull b) {
    asm("fma.rn.f32x2 %0, %1, %2, %0;" : "+l"(d) : "l"(a), "l"(b));
}

// ============ KP: pack weights ============
__global__ void kpack(const float* w1, const float* b1, const float* p1,
                      const float* w2, const float* b2, const float* p2,
                      const float* w3, const float* b3, const float* p3,
                      const float* wa, const float* ba,
                      const float* wb, const float* bb) {
    int t = threadIdx.x;
    for (int i = t; i < 270; i += 256) g_stage[OW1 + i] = w1[i];
    if (t < 10) g_stage[OB1 + t] = b1[t];
    if (t < 10) g_stage[OP1 + t] = p1[t];
    for (int i = t; i < 1440; i += 256) g_stage[OW2 + i] = w2[i];
    if (t < 16) g_stage[OB2 + t] = b2[t];
    if (t < 16) g_stage[OP2 + t] = p2[t];
    for (int i = t; i < 4608; i += 256) g_stage[OW3 + i] = w3[i];
    if (t < 32) g_stage[OB3 + t] = b3[t];
    if (t < 32) g_stage[OP3 + t] = p3[t];
    if (t < 64) g_stage[OWA + t] = wa[t];
    if (t < 2)  g_stage[OBA + t] = ba[t];
    for (int i = t; i < 128; i += 256) g_stage[OWB + i] = wb[i];
    if (t < 4)  g_stage[OBB + t] = bb[t];

    // duplicated-pair constant staging
    for (int i = t; i < 270; i += 256) {
        unsigned u = __float_as_uint(w1[i]);
        g_stage2[i] = ((ull)u << 32) | u;
    }
    if (t < 64) {
        unsigned u = __float_as_uint(wa[t]);
        g_stage2[270 + t] = ((ull)u << 32) | u;
    }
    for (int i = t; i < 128; i += 256) {
        unsigned u = __float_as_uint(wb[i]);
        g_stage2[334 + i] = ((ull)u << 32) | u;
    }

    // k2 duplicated smem-source weights: wd2[(c*16+o)*10 + k] = {w,w}
    float* d2 = (float*)g_wd2;
    for (int idx = t; idx < 1440; idx += 256) {
        int k = idx % 9, rest = idx / 9;
        int o = rest % 16, c = rest / 16;
        float w = w2[o * 90 + c * 9 + k];
        int g = (c * 16 + o) * 10 + k;
        d2[g * 2] = w; d2[g * 2 + 1] = w;
    }
    for (int g = t; g < 160; g += 256) {
        d2[(g * 10 + 9) * 2] = 0.f; d2[(g * 10 + 9) * 2 + 1] = 0.f;
    }
    // k3 duplicated: wd3[(c*32+o)*10 + k] = {w,w}
    float* d3 = (float*)g_wd3;
    for (int idx = t; idx < 4608; idx += 256) {
        int k = idx % 9, rest = idx / 9;
        int o = rest % 32, c = rest / 32;
        float w = w3[o * 144 + c * 9 + k];
        int g = (c * 32 + o) * 10 + k;
        d3[g * 2] = w; d3[g * 2 + 1] = w;
    }
    for (int g = t; g < 512; g += 256) {
        d3[(g * 10 + 9) * 2] = 0.f; d3[(g * 10 + 9) * 2 + 1] = 0.f;
    }
}

// ============ K1: conv1(3->10,3x3) + PReLU + maxpool2, f32x2 ============
__global__ __launch_bounds__(256) void k1(const float* __restrict__ x) {
    int j = blockIdx.x * 16 + threadIdx.x;
    int i = blockIdx.y * 16 + threadIdx.y;
    if (i >= P1 || j >= P1) return;

    ull a01[10], a23[10];   // (row0 px0,px1) and (row1 px0,px1)
#pragma unroll
    for (int co = 0; co < 10; co++) {
        float b = CB1(co);
        a01[co] = pk2(b, b);
        a23[co] = pk2(b, b);
    }

#pragma unroll
    for (int c = 0; c < 3; c++) {
        const float* xp = x + c * H_IN * W_IN + (2 * i) * W_IN + 2 * j;
        ull t2[4][3];
#pragma unroll
        for (int a = 0; a < 4; a++) {
            const float2* rp = reinterpret_cast<const float2*>(xp + a * W_IN);
            float2 u = rp[0], v = rp[1];
            t2[a][0] = pk2(u.x, u.y);
            t2[a][1] = pk2(u.y, v.x);
            t2[a][2] = pk2(v.x, v.y);
        }
#pragma unroll
        for (int co = 0; co < 10; co++)
#pragma unroll
            for (int dy = 0; dy < 3; dy++)
#pragma unroll
                for (int dx = 0; dx < 3; dx++) {
                    ull w = D1(((co * 3 + c) * 3 + dy) * 3 + dx);
                    ffma2(a01[co], t2[dy][dx], w);
                    ffma2(a23[co], t2[dy + 1][dx], w);
                }
    }

#pragma unroll
    for (int co = 0; co < 10; co++) {
        float a00, a01v, a10, a11;
        up2(a00, a01v, a01[co]);
        up2(a10, a11, a23[co]);
        float al = CP1(co);
        a00  = (a00  >= 0.f) ? a00  : al * a00;
        a01v = (a01v >= 0.f) ? a01v : al * a01v;
        a10  = (a10  >= 0.f) ? a10  : al * a10;
        a11  = (a11  >= 0.f) ? a11  : al * a11;
        g_pool1[co * P1 * P1 + i * P1 + j] = fmaxf(fmaxf(a00, a01v), fmaxf(a10, a11));
    }
}

// ============ K2: conv2(10->16) + PReLU, 4 px/thread, f32x2 ============
#define K2_TW 68
#define K2_DATA (10 * 18 * K2_TW)
#define K2_SMEM_BYTES (K2_DATA * 4 + 10 * 16 * 10 * 8)

__global__ __launch_bounds__(256) void k2() {
    extern __shared__ float dy2[];
    float (*s)[18][K2_TW] = (float(*)[18][K2_TW])dy2;
    ull* wsm = (ull*)(dy2 + K2_DATA);

    int tx = threadIdx.x, ty = threadIdx.y;
    int tid = ty * 16 + tx;
    int ox0 = blockIdx.x * 64, oy0 = blockIdx.y * 16;

    {
        float4* wv = (float4*)wsm;
        for (int i = tid; i < 800; i += 256) wv[i] = g_wd2[i];
    }
    for (int idx = tid; idx < 10 * 18 * 66; idx += 256) {
        int c = idx / (18 * 66);
        int rem = idx - c * (18 * 66);
        int r = rem / 66;
        int cc = rem - r * 66;
        int gy = oy0 + r, gx = ox0 + cc;
        s[c][r][cc] = (gy < P1 && gx < P1) ? g_pool1[c * P1 * P1 + gy * P1 + gx] : 0.f;
    }
    __syncthreads();

    int ox = ox0 + tx * 4, oy = oy0 + ty;

    ull accA[16], accB[16];   // (px0,px1) and (px2,px3)
#pragma unroll
    for (int o = 0; o < 16; o++) {
        float b = CB2(o);
        accA[o] = pk2(b, b);
        accB[o] = pk2(b, b);
    }

#pragma unroll 1
    for (int c = 0; c < 10; c++) {
        ull tA[9], tB[9];
#pragma unroll
        for (int r = 0; r < 3; r++) {
            const float* row = &s[c][ty + r][tx * 4];
            float4 A = *reinterpret_cast<const float4*>(row);
            float2 B = *reinterpret_cast<const float2*>(row + 4);
            tA[r * 3 + 0] = pk2(A.x, A.y);
            tA[r * 3 + 1] = pk2(A.y, A.z);
            tA[r * 3 + 2] = pk2(A.z, A.w);
            tB[r * 3 + 0] = pk2(A.z, A.w);
            tB[r * 3 + 1] = pk2(A.w, B.x);
            tB[r * 3 + 2] = pk2(B.x, B.y);
        }
        const ull* wc = wsm + c * 160;
#pragma unroll
        for (int o = 0; o < 16; o++) {
            const ull* w = wc + o * 10;
            ulonglong2 p0 = *(const ulonglong2*)(w + 0);
            ulonglong2 p1 = *(const ulonglong2*)(w + 2);
            ulonglong2 p2 = *(const ulonglong2*)(w + 4);
            ulonglong2 p3 = *(const ulonglong2*)(w + 6);
            ull p8 = w[8];
            ffma2(accA[o], tA[0], p0.x); ffma2(accB[o], tB[0], p0.x);
            ffma2(accA[o], tA[1], p0.y); ffma2(accB[o], tB[1], p0.y);
            ffma2(accA[o], tA[2], p1.x); ffma2(accB[o], tB[2], p1.x);
            ffma2(accA[o], tA[3], p1.y); ffma2(accB[o], tB[3], p1.y);
            ffma2(accA[o], tA[4], p2.x); ffma2(accB[o], tB[4], p2.x);
            ffma2(accA[o], tA[5], p2.y); ffma2(accB[o], tB[5], p2.y);
            ffma2(accA[o], tA[6], p3.x); ffma2(accB[o], tB[6], p3.x);
            ffma2(accA[o], tA[7], p3.y); ffma2(accB[o], tB[7], p3.y);
            ffma2(accA[o], tA[8], p8);   ffma2(accB[o], tB[8], p8);
        }
    }

    if (oy < C2) {
        int base = oy * C2 + ox;
#pragma unroll
        for (int o = 0; o < 16; o++) {
            float v0, v1, v2, v3;
            up2(v0, v1, accA[o]);
            up2(v2, v3, accB[o]);
            float al = CP2(o);
            v0 = (v0 >= 0.f) ? v0 : al * v0;
            v1 = (v1 >= 0.f) ? v1 : al * v1;
            v2 = (v2 >= 0.f) ? v2 : al * v2;
            v3 = (v3 >= 0.f) ? v3 : al * v3;
            float* op = g_h2 + o * C2 * C2 + base;
            if (ox < C2)     op[0] = v0;
            if (ox + 1 < C2) op[1] = v1;
            if (ox + 2 < C2) op[2] = v2;
            if (ox + 3 < C2) op[3] = v3;
        }
    }
}

// ============ K3: conv3(16->32) + PReLU + heads + softmax + hist ============
#define K3_TW 68
#define K3_DATA (16 * 18 * K3_TW)
#define K3_SMEM_BYTES (K3_DATA * 4 + 16 * 32 * 10 * 8)

__global__ __launch_bounds__(256) void k3() {
    extern __shared__ float dy3[];
    float (*s)[18][K3_TW] = (float(*)[18][K3_TW])dy3;
    ull* wsm = (ull*)(dy3 + K3_DATA);

    int tx = threadIdx.x, ty = threadIdx.y;
    int tid = ty * 16 + tx;
    int ox0 = blockIdx.x * 64, oy0 = blockIdx.y * 16;

    {
        float4* wv = (float4*)wsm;
        for (int i = tid; i < 2560; i += 256) wv[i] = g_wd3[i];
    }
    for (int idx = tid; idx < 16 * 18 * 66; idx += 256) {
        int c = idx / (18 * 66);
        int rem = idx - c * (18 * 66);
        int r = rem / 66;
        int cc = rem - r * 66;
        int gy = oy0 + r, gx = ox0 + cc;
        s[c][r][cc] = (gy < C2 && gx < C2) ? g_h2[c * C2 * C2 + gy * C2 + gx] : 0.f;
    }
    __syncthreads();

    int ox = ox0 + tx * 4, oy = oy0 + ty;
    if (oy >= C3) return;

    // head accumulators: [head]{pair01, pair23}, heads = c0,c1,r0,r1,r2,r3
    ull hacc[12];
    {
        float b0 = CBA(0), b1 = CBA(1);
        hacc[0] = pk2(b0, b0); hacc[1] = pk2(b0, b0);
        hacc[2] = pk2(b1, b1); hacc[3] = pk2(b1, b1);
#pragma unroll
        for (int q = 0; q < 4; q++) {
            float b = CBB(q);
            hacc[4 + q * 2] = pk2(b, b);
            hacc[5 + q * 2] = pk2(b, b);
        }
    }

#pragma unroll
    for (int h = 0; h < 2; h++) {
        ull accA[16], accB[16];
#pragma unroll
        for (int oo = 0; oo < 16; oo++) {
            float b = CB3(h * 16 + oo);
            accA[oo] = pk2(b, b);
            accB[oo] = pk2(b, b);
        }

#pragma unroll 1
        for (int c = 0; c < 16; c++) {
            ull tA[9], tB[9];
#pragma unroll
            for (int r = 0; r < 3; r++) {
                const float* row = &s[c][ty + r][tx * 4];
                float4 A = *reinterpret_cast<const float4*>(row);
                float2 B = *reinterpret_cast<const float2*>(row + 4);
                tA[r * 3 + 0] = pk2(A.x, A.y);
                tA[r * 3 + 1] = pk2(A.y, A.z);
                tA[r * 3 + 2] = pk2(A.z, A.w);
                tB[r * 3 + 0] = pk2(A.z, A.w);
                tB[r * 3 + 1] = pk2(A.w, B.x);
                tB[r * 3 + 2] = pk2(B.x, B.y);
            }
            const ull* wc = wsm + (c * 32 + h * 16) * 10;
#pragma unroll
            for (int oo = 0; oo < 16; oo++) {
                const ull* w = wc + oo * 10;
                ulonglong2 p0 = *(const ulonglong2*)(w + 0);
                ulonglong2 p1 = *(const ulonglong2*)(w + 2);
                ulonglong2 p2 = *(const ulonglong2*)(w + 4);
                ulonglong2 p3 = *(const ulonglong2*)(w + 6);
                ull p8 = w[8];
                ffma2(accA[oo], tA[0], p0.x); ffma2(accB[oo], tB[0], p0.x);
                ffma2(accA[oo], tA[1], p0.y); ffma2(accB[oo], tB[1], p0.y);
                ffma2(accA[oo], tA[2], p1.x); ffma2(accB[oo], tB[2], p1.x);
                ffma2(accA[oo], tA[3], p1.y); ffma2(accB[oo], tB[3], p1.y);
                ffma2(accA[oo], tA[4], p2.x); ffma2(accB[oo], tB[4], p2.x);
                ffma2(accA[oo], tA[5], p2.y); ffma2(accB[oo], tB[5], p2.y);
                ffma2(accA[oo], tA[6], p3.x); ffma2(accB[oo], tB[6], p3.x);
                ffma2(accA[oo], tA[7], p3.y); ffma2(accB[oo], tB[7], p3.y);
                ffma2(accA[oo], tA[8], p8);   ffma2(accB[oo], tB[8], p8);
            }
        }

        // PReLU + incremental head accumulation for this half
#pragma unroll
        for (int oo = 0; oo < 16; oo++) {
            int o = h * 16 + oo;
            float v0, v1, v2, v3;
            up2(v0, v1, accA[oo]);
            up2(v2, v3, accB[oo]);
            float al = CP3(o);
            v0 = (v0 >= 0.f) ? v0 : al * v0;
            v1 = (v1 >= 0.f) ? v1 : al * v1;
            v2 = (v2 >= 0.f) ? v2 : al * v2;
            v3 = (v3 >= 0.f) ? v3 : al * v3;
            ull p01 = pk2(v0, v1), p23 = pk2(v2, v3);
            ull wa0 = DWA(o), wa1 = DWA(32 + o);
            ffma2(hacc[0], p01, wa0); ffma2(hacc[1], p23, wa0);
            ffma2(hacc[2], p01, wa1); ffma2(hacc[3], p23, wa1);
#pragma unroll
            for (int q = 0; q < 4; q++) {
                ull wq = DWB(q * 32 + o);
                ffma2(hacc[4 + q * 2], p01, wq);
                ffma2(hacc[5 + q * 2], p23, wq);
            }
        }
    }

    // epilogue: softmax + stores per pixel
    float c0v[4], c1v[4], rv[4][4];
    up2(c0v[0], c0v[1], hacc[0]); up2(c0v[2], c0v[3], hacc[1]);
    up2(c1v[0], c1v[1], hacc[2]); up2(c1v[2], c1v[3], hacc[3]);
#pragma unroll
    for (int q = 0; q < 4; q++) {
        up2(rv[q][0], rv[q][1], hacc[4 + q * 2]);
        up2(rv[q][2], rv[q][3], hacc[5 + q * 2]);
    }

#pragma unroll
    for (int px = 0; px < 4; px++) {
        int oxx = ox + px;
        if (oxx >= C3) break;
        float c0 = c0v[px], c1 = c1v[px];
        float mx = fmaxf(c0, c1);
        float e0 = expf(c0 - mx), e1 = expf(c1 - mx);
        float pr = e1 / (e0 + e1);

        int pix = oy * C3 + oxx;
        g_prob[pix] = pr;
        g_reg[pix] = make_float4(rv[0][px], rv[1][px], rv[2][px], rv[3][px]);

        if (pr >= 0.6f) {
            int bin = (int)((pr - 0.6f) * 20480.f);
            if (bin > NBINS - 1) bin = NBINS - 1;
            atomicAdd(&g_hist[bin], 1);
        }
    }
}

// ============ KH: find histogram cutoff bin ============
__global__ void kh() {
    __shared__ int csum[256];
    int t = threadIdx.x;
    int sum = 0;
    for (int b = t * 32; b < t * 32 + 32; b++) sum += g_hist[b];
    csum[t] = sum;
    __syncthreads();
    int chunk = sum;
    for (int off = 1; off < 256; off <<= 1) {
        int v = csum[t] + ((t + off < 256) ? csum[t + off] : 0);
        __syncthreads();
        csum[t] = v;
        __syncthreads();
    }
    int total = csum[0];
    if (t == 0 && total < KTOP) g_cut = 0;
    int suf_excl = (t < 255) ? csum[t + 1] : 0;
    if (suf_excl < KTOP && suf_excl + chunk >= KTOP) {
        int s = suf_excl;
        int B = t * 32;
        for (int b = t * 32 + 31; b >= t * 32; b--) {
            s += g_hist[b];
            if (s >= KTOP) { B = b; break; }
        }
        g_cut = B;
    }
}

// ============ KC: compact candidates >= cutoff bin ============
__global__ void kc() {
    int i = blockIdx.x * 256 + threadIdx.x;
    if (i >= NPIX) return;
    float pr = g_prob[i];
    if (pr < 0.6f) return;
    int bin = (int)((pr - 0.6f) * 20480.f);
    if (bin > NBINS - 1) bin = NBINS - 1;
    if (bin < g_cut) return;
    int pos = atomicAdd(&g_cnt, 1);
    if (pos < CANDMAX) {
        unsigned long long key =
            ((unsigned long long)__float_as_uint(pr) << 32) |
            (unsigned long long)(~(unsigned)i);
        g_cand[pos] = key;
    }
}

// ============ KS: bitonic sort desc + decode boxes ============
__global__ void ks() {
    __shared__ unsigned long long a[CANDMAX];
    int tid = threadIdx.x;
    int cnt = g_cnt;
    if (cnt > CANDMAX) cnt = CANDMAX;
    for (int i = tid; i < CANDMAX; i += 1024) a[i] = (i < cnt) ? g_cand[i] : 0ULL;
    __syncthreads();

    for (int k = 2; k <= CANDMAX; k <<= 1) {
        for (int j = k >> 1; j > 0; j >>= 1) {
            for (int i = tid; i < CANDMAX; i += 1024) {
                int ixj = i ^ j;
                if (ixj > i) {
                    unsigned long long A = a[i], B = a[ixj];
                    bool desc = ((i & k) == 0);
                    if (desc ? (A < B) : (A > B)) { a[i] = B; a[ixj] = A; }
                }
            }
            __syncthreads();
        }
    }

    if (tid < KTOP) {
        unsigned long long key = a[tid];
        unsigned sb = (unsigned)(key >> 32);
        float sc = sb ? __uint_as_float(sb) : -1.0f;
        float x1 = 0.f, y1 = 0.f, x2 = 0.f, y2 = 0.f;
        if (sc >= 0.6f) {
            unsigned idx = ~(unsigned)(key & 0xFFFFFFFFu);
            float4 rg = g_reg[idx];
            float yy = (float)(idx / C3);
            float xx = (float)(idx % C3);
            float cx = (xx * 2.0f + 6.0f) / 0.6f;
            float cy = (yy * 2.0f + 6.0f) / 0.6f;
            const float ww = 12.0f / 0.6f;
            x1 = cx - ww * 0.5f + rg.x * ww;
            y1 = cy - ww * 0.5f + rg.y * ww;
            x2 = cx + ww * 0.5f + rg.z * ww;
            y2 = cy + ww * 0.5f + rg.w * ww;
        }
        g_box5[tid * 5 + 0] = x1;
        g_box5[tid * 5 + 1] = y1;
        g_box5[tid * 5 + 2] = x2;
        g_box5[tid * 5 + 3] = y2;
        g_box5[tid * 5 + 4] = sc;
    }
}

// ============ KM: build suppression bitmasks ============
__global__ void kmask() {
    int i = blockIdx.x;
    int t = threadIdx.x;
    float ax1 = g_box5[i * 5 + 0], ay1 = g_box5[i * 5 + 1];
    float ax2 = g_box5[i * 5 + 2], ay2 = g_box5[i * 5 + 3];
    float bx1 = g_box5[t * 5 + 0], by1 = g_box5[t * 5 + 1];
    float bx2 = g_box5[t * 5 + 2], by2 = g_box5[t * 5 + 3];
    float aar = (ax2 - ax1) * (ay2 - ay1);
    float bar = (bx2 - bx1) * (by2 - by1);
    float xi1 = fmaxf(ax1, bx1), yi1 = fmaxf(ay1, by1);
    float xi2 = fminf(ax2, bx2), yi2 = fminf(ay2, by2);
    float inter = fmaxf(xi2 - xi1, 0.f) * fmaxf(yi2 - yi1, 0.f);
    float iou = inter / (aar + bar - inter + 1e-9f);
    bool gt = (t > i);
    unsigned b0 = __ballot_sync(0xFFFFFFFFu, gt && (iou > 0.5f));
    unsigned b1 = __ballot_sync(0xFFFFFFFFu, gt && (iou > 0.7f));
    if ((t & 31) == 0) {
        g_mask0[i * 16 + (t >> 5)] = b0;
        g_mask1[i * 16 + (t >> 5)] = b1;
    }
}

// ============ KQ: sequential keep-propagation + output ============
__global__ void kseq(float* __restrict__ out) {
    __shared__ unsigned sm[KTOP * 16];
    __shared__ unsigned skw[16];
    int t = threadIdx.x;
    float x1 = g_box5[t * 5 + 0];
    float y1 = g_box5[t * 5 + 1];
    float x2 = g_box5[t * 5 + 2];
    float y2 = g_box5[t * 5 + 3];
    float sc = g_box5[t * 5 + 4];
    unsigned bal = __ballot_sync(0xFFFFFFFFu, sc >= 0.6f);
    if ((t & 31) == 0) skw[t >> 5] = bal;

    for (int pass = 0; pass < 2; pass++) {
        const unsigned* gm = pass ? g_mask1 : g_mask0;
        for (int i = t; i < KTOP * 16; i += 512) sm[i] = gm[i];
        __syncthreads();
        if (t < 32) {
            unsigned k = (t < 16) ? skw[t] : 0u;
            for (int w = 0; w < 16; w++) {
                unsigned done = 0;
                while (true) {
                    unsigned cur = __shfl_sync(0xFFFFFFFFu, k, w) & ~done;
                    if (!cur) break;
                    int b = __ffs(cur) - 1;
                    done |= (1u << b);
                    int i = w * 32 + b;
                    unsigned m = (t < 16) ? sm[i * 16 + t] : 0u;
                    k &= ~m;
                }
            }
            if (t < 16) skw[t] = k;
        }
        __syncthreads();
    }

    float m = ((skw[t >> 5] >> (t & 31)) & 1u) ? 1.f : 0.f;
    out[t * 5 + 0] = x1 * m;
    out[t * 5 + 1] = y1 * m;
    out[t * 5 + 2] = x2 * m;
    out[t * 5 + 3] = y2 * m;
    out[t * 5 + 4] = sc * m;
}

// ---------------- host launcher ----------------
extern "C" void kernel_launch(void* const* d_in, const int* in_sizes, int n_in,
                              void* d_out, int out_size) {
    const float* x = (const float*)d_in[0];

    kpack<<<1, 256>>>((const float*)d_in[1], (const float*)d_in[2], (const float*)d_in[3],
                      (const float*)d_in[4], (const float*)d_in[5], (const float*)d_in[6],
                      (const float*)d_in[7], (const float*)d_in[8], (const float*)d_in[9],
                      (const float*)d_in[10], (const float*)d_in[11],
                      (const float*)d_in[12], (const float*)d_in[13]);

    void* sp = 0; cudaGetSymbolAddress(&sp, g_stage);
    cudaMemcpyToSymbolAsync(cAll, sp, NCONST * sizeof(float), 0, cudaMemcpyDeviceToDevice);
    void* sp2 = 0; cudaGetSymbolAddress(&sp2, g_stage2);
    cudaMemcpyToSymbolAsync(cDup, sp2, 462 * sizeof(ull), 0, cudaMemcpyDeviceToDevice);

    void* hp = 0; cudaGetSymbolAddress(&hp, g_hist);
    cudaMemsetAsync(hp, 0, NBINS * sizeof(int));
    void* cp = 0; cudaGetSymbolAddress(&cp, g_cnt);
    cudaMemsetAsync(cp, 0, sizeof(int));

    cudaFuncSetAttribute(k2, cudaFuncAttributeMaxDynamicSharedMemorySize, K2_SMEM_BYTES);
    cudaFuncSetAttribute(k3, cudaFuncAttributeMaxDynamicSharedMemorySize, K3_SMEM_BYTES);

    dim3 b16(16, 16);
    k1<<<dim3(64, 64), b16>>>(x);
    k2<<<dim3(16, 64), b16, K2_SMEM_BYTES>>>();
    k3<<<dim3(16, 64), b16, K3_SMEM_BYTES>>>();
    kh<<<1, 256>>>();
    kc<<<(NPIX + 255) / 256, 256>>>();
    ks<<<1, 1024>>>();
    kmask<<<KTOP, KTOP>>>();
    kseq<<<1, 512>>>((float*)d_out);
}

// round 7
// speedup vs baseline: 1.1326x; 1.1326x over previous
#include <cuda_runtime.h>
#include <math.h>
#include <stdint.h>

// ---------------- problem constants ----------------
#define H_IN 2048
#define W_IN 2048
#define P1   1023            // after conv1(2046) + maxpool2
#define C2   1021            // after conv2
#define H2S  1024            // padded row stride for h2
#define C3   1019            // after conv3
#define NPIX (C3*C3)         // 1038361
#define NBINS 8192
#define CANDMAX 4096
#define KTOP 512

typedef unsigned long long ull;

// ---------------- scratch (device globals) ----------
__device__ float g_pool1[10 * P1 * P1];
__device__ float g_h2p[16 * C2 * H2S];      // padded stride 1024
__device__ float g_prob[NPIX];
__device__ float4 g_reg[NPIX];
__device__ int   g_hist[NBINS];
__device__ int   g_cut;
__device__ int   g_cnt;
__device__ unsigned long long g_cand[CANDMAX];
__device__ float g_box5[KTOP * 5];
__device__ unsigned g_mask0[KTOP * 16];
__device__ unsigned g_mask1[KTOP * 16];
__device__ float g_stage[6632];
__device__ ull   g_stage2[462];
// duplicated {w,w} weights, padded to 10 per (c,o) group for 16B-aligned LDS.128
__device__ float4 g_wd2[10 * 16 * 10 / 2];   // 800 float4
__device__ float4 g_wd3[16 * 32 * 10 / 2];   // 2560 float4

// ---------------- packed constant scalars -------
#define OW1 0
#define OB1 270
#define OP1 280
#define OW2 290
#define OB2 1730
#define OP2 1746
#define OW3 1762
#define OB3 6370
#define OP3 6402
#define OWA 6434
#define OBA 6498
#define OWB 6500
#define OBB 6628
#define NCONST 6632
__constant__ float cAll[NCONST];
__constant__ ull cDup[462];   // k1 weights (270), head wa (64), head wb (128)

#define CB1(i) cAll[OB1 + (i)]
#define CP1(i) cAll[OP1 + (i)]
#define CB2(i) cAll[OB2 + (i)]
#define CP2(i) cAll[OP2 + (i)]
#define CB3(i) cAll[OB3 + (i)]
#define CP3(i) cAll[OP3 + (i)]
#define CBA(i) cAll[OBA + (i)]
#define CBB(i) cAll[OBB + (i)]
#define D1(i)  cDup[(i)]
#define DWA(i) cDup[270 + (i)]
#define DWB(i) cDup[334 + (i)]

// ---------------- f32x2 helpers ----------------
__device__ __forceinline__ ull pk2(float lo, float hi) {
    ull r; asm("mov.b64 %0, {%1, %2};" : "=l"(r) : "f"(lo), "f"(hi)); return r;
}
__device__ __forceinline__ void up2(float& lo, float& hi, ull v) {
    asm("mov.b64 {%0, %1}, %2;" : "=f"(lo), "=f"(hi) : "l"(v));
}
__device__ __forceinline__ void ffma2(ull& d, ull a, ull b) {
    asm("fma.rn.f32x2 %0, %1, %2, %0;" : "+l"(d) : "l"(a), "l"(b));
}

// ============ KP: pack weights ============
__global__ void kpack(const float* w1, const float* b1, const float* p1,
                      const float* w2, const float* b2, const float* p2,
                      const float* w3, const float* b3, const float* p3,
                      const float* wa, const float* ba,
                      const float* wb, const float* bb) {
    int t = threadIdx.x;
    for (int i = t; i < 270; i += 256) g_stage[OW1 + i] = w1[i];
    if (t < 10) g_stage[OB1 + t] = b1[t];
    if (t < 10) g_stage[OP1 + t] = p1[t];
    for (int i = t; i < 1440; i += 256) g_stage[OW2 + i] = w2[i];
    if (t < 16) g_stage[OB2 + t] = b2[t];
    if (t < 16) g_stage[OP2 + t] = p2[t];
    for (int i = t; i < 4608; i += 256) g_stage[OW3 + i] = w3[i];
    if (t < 32) g_stage[OB3 + t] = b3[t];
    if (t < 32) g_stage[OP3 + t] = p3[t];
    if (t < 64) g_stage[OWA + t] = wa[t];
    if (t < 2)  g_stage[OBA + t] = ba[t];
    for (int i = t; i < 128; i += 256) g_stage[OWB + i] = wb[i];
    if (t < 4)  g_stage[OBB + t] = bb[t];

    for (int i = t; i < 270; i += 256) {
        unsigned u = __float_as_uint(w1[i]);
        g_stage2[i] = ((ull)u << 32) | u;
    }
    if (t < 64) {
        unsigned u = __float_as_uint(wa[t]);
        g_stage2[270 + t] = ((ull)u << 32) | u;
    }
    for (int i = t; i < 128; i += 256) {
        unsigned u = __float_as_uint(wb[i]);
        g_stage2[334 + i] = ((ull)u << 32) | u;
    }

    // k2: wd2[(c*16+o)*10 + k] = {w,w}
    float* d2 = (float*)g_wd2;
    for (int idx = t; idx < 1440; idx += 256) {
        int k = idx % 9, rest = idx / 9;
        int o = rest % 16, c = rest / 16;
        float w = w2[o * 90 + c * 9 + k];
        int g = (c * 16 + o) * 10 + k;
        d2[g * 2] = w; d2[g * 2 + 1] = w;
    }
    for (int g = t; g < 160; g += 256) {
        d2[(g * 10 + 9) * 2] = 0.f; d2[(g * 10 + 9) * 2 + 1] = 0.f;
    }
    // k3: wd3[(c*32+o)*10 + k] = {w,w}
    float* d3 = (float*)g_wd3;
    for (int idx = t; idx < 4608; idx += 256) {
        int k = idx % 9, rest = idx / 9;
        int o = rest % 32, c = rest / 32;
        float w = w3[o * 144 + c * 9 + k];
        int g = (c * 32 + o) * 10 + k;
        d3[g * 2] = w; d3[g * 2 + 1] = w;
    }
    for (int g = t; g < 512; g += 256) {
        d3[(g * 10 + 9) * 2] = 0.f; d3[(g * 10 + 9) * 2 + 1] = 0.f;
    }
}

// ============ K1: conv1(3->10,3x3) + PReLU + maxpool2, f32x2 ============
__global__ __launch_bounds__(256) void k1(const float* __restrict__ x) {
    int j = blockIdx.x * 16 + threadIdx.x;
    int i = blockIdx.y * 16 + threadIdx.y;
    if (i >= P1 || j >= P1) return;

    ull a01[10], a23[10];
#pragma unroll
    for (int co = 0; co < 10; co++) {
        float b = CB1(co);
        a01[co] = pk2(b, b);
        a23[co] = pk2(b, b);
    }

#pragma unroll
    for (int c = 0; c < 3; c++) {
        const float* xp = x + c * H_IN * W_IN + (2 * i) * W_IN + 2 * j;
        ull t2[4][3];
#pragma unroll
        for (int a = 0; a < 4; a++) {
            const float2* rp = reinterpret_cast<const float2*>(xp + a * W_IN);
            float2 u = rp[0], v = rp[1];
            t2[a][0] = pk2(u.x, u.y);
            t2[a][1] = pk2(u.y, v.x);
            t2[a][2] = pk2(v.x, v.y);
        }
#pragma unroll
        for (int co = 0; co < 10; co++)
#pragma unroll
            for (int dy = 0; dy < 3; dy++)
#pragma unroll
                for (int dx = 0; dx < 3; dx++) {
                    ull w = D1(((co * 3 + c) * 3 + dy) * 3 + dx);
                    ffma2(a01[co], t2[dy][dx], w);
                    ffma2(a23[co], t2[dy + 1][dx], w);
                }
    }

#pragma unroll
    for (int co = 0; co < 10; co++) {
        float a00, a01v, a10, a11;
        up2(a00, a01v, a01[co]);
        up2(a10, a11, a23[co]);
        float al = CP1(co);
        a00  = (a00  >= 0.f) ? a00  : al * a00;
        a01v = (a01v >= 0.f) ? a01v : al * a01v;
        a10  = (a10  >= 0.f) ? a10  : al * a10;
        a11  = (a11  >= 0.f) ? a11  : al * a11;
        g_pool1[co * P1 * P1 + i * P1 + j] = fmaxf(fmaxf(a00, a01v), fmaxf(a10, a11));
    }
}

// ============ K2: conv2(10->16) + PReLU, 4 px/thread, 128-thr blocks ======
#define K2_TW 36
#define K2_DATA (10 * 18 * K2_TW)            // 6480 floats
#define K2_SMEM_BYTES (K2_DATA * 4 + 10 * 16 * 10 * 8)   // 25920 + 12800

__global__ __launch_bounds__(128, 4) void k2() {
    extern __shared__ float dy2[];
    float (*s)[18][K2_TW] = (float(*)[18][K2_TW])dy2;
    ull* wsm = (ull*)(dy2 + K2_DATA);

    int tx = threadIdx.x, ty = threadIdx.y;       // 8 x 16
    int tid = ty * 8 + tx;
    int ox0 = blockIdx.x * 32, oy0 = blockIdx.y * 16;

    {
        float4* wv = (float4*)wsm;
        for (int i = tid; i < 800; i += 128) wv[i] = g_wd2[i];
    }
    for (int idx = tid; idx < 10 * 18 * 34; idx += 128) {
        int c = idx / (18 * 34);
        int rem = idx - c * (18 * 34);
        int r = rem / 34;
        int cc = rem - r * 34;
        int gy = oy0 + r, gx = ox0 + cc;
        s[c][r][cc] = (gy < P1 && gx < P1) ? g_pool1[c * P1 * P1 + gy * P1 + gx] : 0.f;
    }
    __syncthreads();

    int ox = ox0 + tx * 4, oy = oy0 + ty;

    ull accA[16], accB[16];
#pragma unroll
    for (int o = 0; o < 16; o++) {
        float b = CB2(o);
        accA[o] = pk2(b, b);
        accB[o] = pk2(b, b);
    }

#pragma unroll 1
    for (int c = 0; c < 10; c++) {
        ull q[3][5];
#pragma unroll
        for (int r = 0; r < 3; r++) {
            const float* row = &s[c][ty + r][tx * 4];
            float4 A = *reinterpret_cast<const float4*>(row);
            float2 B = *reinterpret_cast<const float2*>(row + 4);
            q[r][0] = pk2(A.x, A.y);
            q[r][1] = pk2(A.y, A.z);
            q[r][2] = pk2(A.z, A.w);
            q[r][3] = pk2(A.w, B.x);
            q[r][4] = pk2(B.x, B.y);
        }
        const ull* wc = wsm + c * 160;
#pragma unroll
        for (int o = 0; o < 16; o++) {
            const ull* w = wc + o * 10;
            ulonglong2 p0 = *(const ulonglong2*)(w + 0);
            ulonglong2 p1 = *(const ulonglong2*)(w + 2);
            ulonglong2 p2 = *(const ulonglong2*)(w + 4);
            ulonglong2 p3 = *(const ulonglong2*)(w + 6);
            ull p8 = w[8];
            ffma2(accA[o], q[0][0], p0.x); ffma2(accB[o], q[0][2], p0.x);
            ffma2(accA[o], q[0][1], p0.y); ffma2(accB[o], q[0][3], p0.y);
            ffma2(accA[o], q[0][2], p1.x); ffma2(accB[o], q[0][4], p1.x);
            ffma2(accA[o], q[1][0], p1.y); ffma2(accB[o], q[1][2], p1.y);
            ffma2(accA[o], q[1][1], p2.x); ffma2(accB[o], q[1][3], p2.x);
            ffma2(accA[o], q[1][2], p2.y); ffma2(accB[o], q[1][4], p2.y);
            ffma2(accA[o], q[2][0], p3.x); ffma2(accB[o], q[2][2], p3.x);
            ffma2(accA[o], q[2][1], p3.y); ffma2(accB[o], q[2][3], p3.y);
            ffma2(accA[o], q[2][2], p8);   ffma2(accB[o], q[2][4], p8);
        }
    }

    if (oy < C2) {
        int base = oy * H2S + ox;
#pragma unroll
        for (int o = 0; o < 16; o++) {
            float v0, v1, v2, v3;
            up2(v0, v1, accA[o]);
            up2(v2, v3, accB[o]);
            float al = CP2(o);
            v0 = (v0 >= 0.f) ? v0 : al * v0;
            v1 = (v1 >= 0.f) ? v1 : al * v1;
            v2 = (v2 >= 0.f) ? v2 : al * v2;
            v3 = (v3 >= 0.f) ? v3 : al * v3;
            float* op = g_h2p + o * (C2 * H2S) + base;
            if (ox + 3 < C2) {
                *reinterpret_cast<float4*>(op) = make_float4(v0, v1, v2, v3);
            } else {
                if (ox < C2)     op[0] = v0;
                if (ox + 1 < C2) op[1] = v1;
                if (ox + 2 < C2) op[2] = v2;
                if (ox + 3 < C2) op[3] = v3;
            }
        }
    }
}

// ============ K3: conv3(16->32) + PReLU + heads + softmax + hist ==========
#define K3_TW 36
#define K3_DATA (16 * 18 * K3_TW)            // 10368 floats = 41472 B
#define K3_WHALF 2560                        // ull per 16-channel half
#define K3_SMEM_BYTES (K3_DATA * 4 + K3_WHALF * 8)   // 41472 + 20480 = 61952

__global__ __launch_bounds__(128, 3) void k3() {
    extern __shared__ float dy3[];
    float (*s)[18][K3_TW] = (float(*)[18][K3_TW])dy3;
    ull* wsm = (ull*)(dy3 + K3_DATA);

    int tx = threadIdx.x, ty = threadIdx.y;       // 8 x 16
    int tid = ty * 8 + tx;
    int ox0 = blockIdx.x * 32, oy0 = blockIdx.y * 16;

    for (int idx = tid; idx < 16 * 18 * 34; idx += 128) {
        int c = idx / (18 * 34);
        int rem = idx - c * (18 * 34);
        int r = rem / 34;
        int cc = rem - r * 34;
        int gy = oy0 + r, gx = ox0 + cc;
        s[c][r][cc] = (gy < C2 && gx < C2) ? g_h2p[c * (C2 * H2S) + gy * H2S + gx] : 0.f;
    }

    int ox = ox0 + tx * 4, oy = oy0 + ty;

    // head accumulators: c0,c1 then r0..r3, each {pair01, pair23}
    ull hacc[12];
    {
        float b0 = CBA(0), b1 = CBA(1);
        hacc[0] = pk2(b0, b0); hacc[1] = pk2(b0, b0);
        hacc[2] = pk2(b1, b1); hacc[3] = pk2(b1, b1);
#pragma unroll
        for (int qq = 0; qq < 4; qq++) {
            float b = CBB(qq);
            hacc[4 + qq * 2] = pk2(b, b);
            hacc[5 + qq * 2] = pk2(b, b);
        }
    }

#pragma unroll 1
    for (int h = 0; h < 2; h++) {
        __syncthreads();   // h=0: tile ready; h=1: previous-half compute done
        {
            float4* wv = (float4*)wsm;
            for (int i = tid; i < 1280; i += 128) {
                int g2 = i / 5, k4 = i - g2 * 5;
                int c = g2 >> 4, oo = g2 & 15;
                wv[i] = g_wd3[(c * 32 + h * 16 + oo) * 5 + k4];
            }
        }
        __syncthreads();

        ull accA[16], accB[16];
#pragma unroll
        for (int oo = 0; oo < 16; oo++) {
            float b = CB3(h * 16 + oo);
            accA[oo] = pk2(b, b);
            accB[oo] = pk2(b, b);
        }

#pragma unroll 1
        for (int c = 0; c < 16; c++) {
            ull q[3][5];
#pragma unroll
            for (int r = 0; r < 3; r++) {
                const float* row = &s[c][ty + r][tx * 4];
                float4 A = *reinterpret_cast<const float4*>(row);
                float2 B = *reinterpret_cast<const float2*>(row + 4);
                q[r][0] = pk2(A.x, A.y);
                q[r][1] = pk2(A.y, A.z);
                q[r][2] = pk2(A.z, A.w);
                q[r][3] = pk2(A.w, B.x);
                q[r][4] = pk2(B.x, B.y);
            }
            const ull* wc = wsm + c * 160;
#pragma unroll
            for (int oo = 0; oo < 16; oo++) {
                const ull* w = wc + oo * 10;
                ulonglong2 p0 = *(const ulonglong2*)(w + 0);
                ulonglong2 p1 = *(const ulonglong2*)(w + 2);
                ulonglong2 p2 = *(const ulonglong2*)(w + 4);
                ulonglong2 p3 = *(const ulonglong2*)(w + 6);
                ull p8 = w[8];
                ffma2(accA[oo], q[0][0], p0.x); ffma2(accB[oo], q[0][2], p0.x);
                ffma2(accA[oo], q[0][1], p0.y); ffma2(accB[oo], q[0][3], p0.y);
                ffma2(accA[oo], q[0][2], p1.x); ffma2(accB[oo], q[0][4], p1.x);
                ffma2(accA[oo], q[1][0], p1.y); ffma2(accB[oo], q[1][2], p1.y);
                ffma2(accA[oo], q[1][1], p2.x); ffma2(accB[oo], q[1][3], p2.x);
                ffma2(accA[oo], q[1][2], p2.y); ffma2(accB[oo], q[1][4], p2.y);
                ffma2(accA[oo], q[2][0], p3.x); ffma2(accB[oo], q[2][2], p3.x);
                ffma2(accA[oo], q[2][1], p3.y); ffma2(accB[oo], q[2][3], p3.y);
                ffma2(accA[oo], q[2][2], p8);   ffma2(accB[oo], q[2][4], p8);
            }
        }

        // PReLU + incremental head accumulation for this half
#pragma unroll
        for (int oo = 0; oo < 16; oo++) {
            int o = h * 16 + oo;
            float v0, v1, v2, v3;
            up2(v0, v1, accA[oo]);
            up2(v2, v3, accB[oo]);
            float al = CP3(o);
            v0 = (v0 >= 0.f) ? v0 : al * v0;
            v1 = (v1 >= 0.f) ? v1 : al * v1;
            v2 = (v2 >= 0.f) ? v2 : al * v2;
            v3 = (v3 >= 0.f) ? v3 : al * v3;
            ull p01 = pk2(v0, v1), p23 = pk2(v2, v3);
            ull wa0 = DWA(o), wa1 = DWA(32 + o);
            ffma2(hacc[0], p01, wa0); ffma2(hacc[1], p23, wa0);
            ffma2(hacc[2], p01, wa1); ffma2(hacc[3], p23, wa1);
#pragma unroll
            for (int qq = 0; qq < 4; qq++) {
                ull wq = DWB(qq * 32 + o);
                ffma2(hacc[4 + qq * 2], p01, wq);
                ffma2(hacc[5 + qq * 2], p23, wq);
            }
        }
    }

    if (oy >= C3) return;

    float c0v[4], c1v[4], rv[4][4];
    up2(c0v[0], c0v[1], hacc[0]); up2(c0v[2], c0v[3], hacc[1]);
    up2(c1v[0], c1v[1], hacc[2]); up2(c1v[2], c1v[3], hacc[3]);
#pragma unroll
    for (int qq = 0; qq < 4; qq++) {
        up2(rv[qq][0], rv[qq][1], hacc[4 + qq * 2]);
        up2(rv[qq][2], rv[qq][3], hacc[5 + qq * 2]);
    }

#pragma unroll
    for (int px = 0; px < 4; px++) {
        int oxx = ox + px;
        if (oxx >= C3) break;
        float c0 = c0v[px], c1 = c1v[px];
        float mx = fmaxf(c0, c1);
        float e0 = expf(c0 - mx), e1 = expf(c1 - mx);
        float pr = e1 / (e0 + e1);

        int pix = oy * C3 + oxx;
        g_prob[pix] = pr;
        g_reg[pix] = make_float4(rv[0][px], rv[1][px], rv[2][px], rv[3][px]);

        if (pr >= 0.6f) {
            int bin = (int)((pr - 0.6f) * 20480.f);
            if (bin > NBINS - 1) bin = NBINS - 1;
            atomicAdd(&g_hist[bin], 1);
        }
    }
}

// ============ KH: find histogram cutoff bin ============
__global__ void kh() {
    __shared__ int csum[256];
    int t = threadIdx.x;
    int sum = 0;
    for (int b = t * 32; b < t * 32 + 32; b++) sum += g_hist[b];
    csum[t] = sum;
    __syncthreads();
    int chunk = sum;
    for (int off = 1; off < 256; off <<= 1) {
        int v = csum[t] + ((t + off < 256) ? csum[t + off] : 0);
        __syncthreads();
        csum[t] = v;
        __syncthreads();
    }
    int total = csum[0];
    if (t == 0 && total < KTOP) g_cut = 0;
    int suf_excl = (t < 255) ? csum[t + 1] : 0;
    if (suf_excl < KTOP && suf_excl + chunk >= KTOP) {
        int s = suf_excl;
        int B = t * 32;
        for (int b = t * 32 + 31; b >= t * 32; b--) {
            s += g_hist[b];
            if (s >= KTOP) { B = b; break; }
        }
        g_cut = B;
    }
}

// ============ KC: compact candidates >= cutoff bin ============
__global__ void kc() {
    int i = blockIdx.x * 256 + threadIdx.x;
    if (i >= NPIX) return;
    float pr = g_prob[i];
    if (pr < 0.6f) return;
    int bin = (int)((pr - 0.6f) * 20480.f);
    if (bin > NBINS - 1) bin = NBINS - 1;
    if (bin < g_cut) return;
    int pos = atomicAdd(&g_cnt, 1);
    if (pos < CANDMAX) {
        unsigned long long key =
            ((unsigned long long)__float_as_uint(pr) << 32) |
            (unsigned long long)(~(unsigned)i);
        g_cand[pos] = key;
    }
}

// ============ KS: bitonic sort desc + decode boxes ============
__global__ void ks() {
    __shared__ unsigned long long a[CANDMAX];
    int tid = threadIdx.x;
    int cnt = g_cnt;
    if (cnt > CANDMAX) cnt = CANDMAX;
    for (int i = tid; i < CANDMAX; i += 1024) a[i] = (i < cnt) ? g_cand[i] : 0ULL;
    __syncthreads();

    for (int k = 2; k <= CANDMAX; k <<= 1) {
        for (int j = k >> 1; j > 0; j >>= 1) {
            for (int i = tid; i < CANDMAX; i += 1024) {
                int ixj = i ^ j;
                if (ixj > i) {
                    unsigned long long A = a[i], B = a[ixj];
                    bool desc = ((i & k) == 0);
                    if (desc ? (A < B) : (A > B)) { a[i] = B; a[ixj] = A; }
                }
            }
            __syncthreads();
        }
    }

    if (tid < KTOP) {
        unsigned long long key = a[tid];
        unsigned sb = (unsigned)(key >> 32);
        float sc = sb ? __uint_as_float(sb) : -1.0f;
        float x1 = 0.f, y1 = 0.f, x2 = 0.f, y2 = 0.f;
        if (sc >= 0.6f) {
            unsigned idx = ~(unsigned)(key & 0xFFFFFFFFu);
            float4 rg = g_reg[idx];
            float yy = (float)(idx / C3);
            float xx = (float)(idx % C3);
            float cx = (xx * 2.0f + 6.0f) / 0.6f;
            float cy = (yy * 2.0f + 6.0f) / 0.6f;
            const float ww = 12.0f / 0.6f;
            x1 = cx - ww * 0.5f + rg.x * ww;
            y1 = cy - ww * 0.5f + rg.y * ww;
            x2 = cx + ww * 0.5f + rg.z * ww;
            y2 = cy + ww * 0.5f + rg.w * ww;
        }
        g_box5[tid * 5 + 0] = x1;
        g_box5[tid * 5 + 1] = y1;
        g_box5[tid * 5 + 2] = x2;
        g_box5[tid * 5 + 3] = y2;
        g_box5[tid * 5 + 4] = sc;
    }
}

// ============ KM: build suppression bitmasks ============
__global__ void kmask() {
    int i = blockIdx.x;
    int t = threadIdx.x;
    float ax1 = g_box5[i * 5 + 0], ay1 = g_box5[i * 5 + 1];
    float ax2 = g_box5[i * 5 + 2], ay2 = g_box5[i * 5 + 3];
    float bx1 = g_box5[t * 5 + 0], by1 = g_box5[t * 5 + 1];
    float bx2 = g_box5[t * 5 + 2], by2 = g_box5[t * 5 + 3];
    float aar = (ax2 - ax1) * (ay2 - ay1);
    float bar = (bx2 - bx1) * (by2 - by1);
    float xi1 = fmaxf(ax1, bx1), yi1 = fmaxf(ay1, by1);
    float xi2 = fminf(ax2, bx2), yi2 = fminf(ay2, by2);
    float inter = fmaxf(xi2 - xi1, 0.f) * fmaxf(yi2 - yi1, 0.f);
    float iou = inter / (aar + bar - inter + 1e-9f);
    bool gt = (t > i);
    unsigned b0 = __ballot_sync(0xFFFFFFFFu, gt && (iou > 0.5f));
    unsigned b1 = __ballot_sync(0xFFFFFFFFu, gt && (iou > 0.7f));
    if ((t & 31) == 0) {
        g_mask0[i * 16 + (t >> 5)] = b0;
        g_mask1[i * 16 + (t >> 5)] = b1;
    }
}

// ============ KQ: sequential keep-propagation + output ============
__global__ void kseq(float* __restrict__ out) {
    __shared__ unsigned sm[KTOP * 16];
    __shared__ unsigned skw[16];
    int t = threadIdx.x;
    float x1 = g_box5[t * 5 + 0];
    float y1 = g_box5[t * 5 + 1];
    float x2 = g_box5[t * 5 + 2];
    float y2 = g_box5[t * 5 + 3];
    float sc = g_box5[t * 5 + 4];
    unsigned bal = __ballot_sync(0xFFFFFFFFu, sc >= 0.6f);
    if ((t & 31) == 0) skw[t >> 5] = bal;

    for (int pass = 0; pass < 2; pass++) {
        const unsigned* gm = pass ? g_mask1 : g_mask0;
        for (int i = t; i < KTOP * 16; i += 512) sm[i] = gm[i];
        __syncthreads();
        if (t < 32) {
            unsigned k = (t < 16) ? skw[t] : 0u;
            for (int w = 0; w < 16; w++) {
                unsigned done = 0;
                while (true) {
                    unsigned cur = __shfl_sync(0xFFFFFFFFu, k, w) & ~done;
                    if (!cur) break;
                    int b = __ffs(cur) - 1;
                    done |= (1u << b);
                    int i = w * 32 + b;
                    unsigned m = (t < 16) ? sm[i * 16 + t] : 0u;
                    k &= ~m;
                }
            }
            if (t < 16) skw[t] = k;
        }
        __syncthreads();
    }

    float m = ((skw[t >> 5] >> (t & 31)) & 1u) ? 1.f : 0.f;
    out[t * 5 + 0] = x1 * m;
    out[t * 5 + 1] = y1 * m;
    out[t * 5 + 2] = x2 * m;
    out[t * 5 + 3] = y2 * m;
    out[t * 5 + 4] = sc * m;
}

// ---------------- host launcher ----------------
extern "C" void kernel_launch(void* const* d_in, const int* in_sizes, int n_in,
                              void* d_out, int out_size) {
    const float* x = (const float*)d_in[0];

    kpack<<<1, 256>>>((const float*)d_in[1], (const float*)d_in[2], (const float*)d_in[3],
                      (const float*)d_in[4], (const float*)d_in[5], (const float*)d_in[6],
                      (const float*)d_in[7], (const float*)d_in[8], (const float*)d_in[9],
                      (const float*)d_in[10], (const float*)d_in[11],
                      (const float*)d_in[12], (const float*)d_in[13]);

    void* sp = 0; cudaGetSymbolAddress(&sp, g_stage);
    cudaMemcpyToSymbolAsync(cAll, sp, NCONST * sizeof(float), 0, cudaMemcpyDeviceToDevice);
    void* sp2 = 0; cudaGetSymbolAddress(&sp2, g_stage2);
    cudaMemcpyToSymbolAsync(cDup, sp2, 462 * sizeof(ull), 0, cudaMemcpyDeviceToDevice);

    void* hp = 0; cudaGetSymbolAddress(&hp, g_hist);
    cudaMemsetAsync(hp, 0, NBINS * sizeof(int));
    void* cp = 0; cudaGetSymbolAddress(&cp, g_cnt);
    cudaMemsetAsync(cp, 0, sizeof(int));

    cudaFuncSetAttribute(k2, cudaFuncAttributeMaxDynamicSharedMemorySize, K2_SMEM_BYTES);
    cudaFuncSetAttribute(k3, cudaFuncAttributeMaxDynamicSharedMemorySize, K3_SMEM_BYTES);

    dim3 b128(8, 16);
    k1<<<dim3(64, 64), dim3(16, 16)>>>(x);
    k2<<<dim3(32, 64), b128, K2_SMEM_BYTES>>>();
    k3<<<dim3(32, 64), b128, K3_SMEM_BYTES>>>();
    kh<<<1, 256>>>();
    kc<<<(NPIX + 255) / 256, 256>>>();
    ks<<<1, 1024>>>();
    kmask<<<KTOP, KTOP>>>();
    kseq<<<1, 512>>>((float*)d_out);
}